// round 13
// baseline (speedup 1.0000x reference)
#include <cuda_runtime.h>
#include <stdint.h>

#define N_NODES 10000
#define N_EDGES 320000
#define HID 128
#define H3 384
#define NRBF 20
#define EPB 96      // edges per block (edge kernel): 6 m16-tiles
#define NPB 32      // nodes per block (node kernel)
#define KCH 16      // weight k-rows per staged chunk
#define NCHUNK (HID / KCH)   // 8
#define EK_THREADS 512
#define NWBUF 3     // staging buffers (3-deep pipeline)

typedef unsigned long long ull;

// scratch
__device__ float g_x[N_NODES * H3];     // node MLP output [N, 384]
__device__ float g_wf2t[HID * H3];      // Wf2 as tf32 bits
__device__ float g_w1t[HID * H3];       // W1 as tf32 bits
__device__ float g_w2t[H3 * H3];        // W2 as tf32 bits
__device__ int g_idx64;
__device__ int g_hist[N_NODES];
__device__ int g_cursor[N_NODES];
__device__ int g_perm[N_EDGES];         // edge ids sorted by target

__device__ __forceinline__ float silu_f(float v) {
    return v / (1.0f + __expf(-v));
}
__device__ __forceinline__ ull pack2(float lo, float hi) {
    ull r;
    asm("mov.b64 %0,{%1,%2};" : "=l"(r) : "f"(lo), "f"(hi));
    return r;
}
__device__ __forceinline__ uint32_t f2tf32(float f) {
    uint32_t r;
    asm("cvt.rna.tf32.f32 %0,%1;" : "=r"(r) : "f"(f));
    return r;
}
__device__ __forceinline__ void mma_tf32(float* d, const uint32_t* a, const uint32_t* b) {
    asm("mma.sync.aligned.m16n8k8.row.col.f32.tf32.tf32.f32 "
        "{%0,%1,%2,%3},{%4,%5,%6,%7},{%8,%9},{%0,%1,%2,%3};"
        : "+f"(d[0]), "+f"(d[1]), "+f"(d[2]), "+f"(d[3])
        : "r"(a[0]), "r"(a[1]), "r"(a[2]), "r"(a[3]), "r"(b[0]), "r"(b[1]));
}
__device__ __forceinline__ void red_add_v2(float* p, float a, float b) {
    asm volatile("red.global.add.v2.f32 [%0],{%1,%2};"
                 :: "l"(p), "f"(a), "f"(b) : "memory");
}
__device__ __forceinline__ void cp_async16(void* sdst, const void* gsrc) {
    unsigned s = (unsigned)__cvta_generic_to_shared(sdst);
    asm volatile("cp.async.cg.shared.global [%0],[%1],16;" :: "r"(s), "l"(gsrc));
}
__device__ __forceinline__ void cp_commit() {
    asm volatile("cp.async.commit_group;");
}
template <int N>
__device__ __forceinline__ void cp_wait() {
    asm volatile("cp.async.wait_group %0;" :: "n"(N));
}

// sorted position s for physical MMA row R (bijection on [0,96))
// R = 16*mt + 8*half + g  <->  s = 12*g + 2*mt + half
__device__ __forceinline__ int sorted_of_row(int R) {
    return 12 * (R & 7) + ((R >> 4) << 1) + ((R >> 3) & 1);
}

// ---------------------------------------------------------------------------
// Kernel 1: out = concat(q, mu); idx dtype; zero hist; tf32-convert weights.
// ---------------------------------------------------------------------------
__global__ void init_out(const float* __restrict__ q,
                         const float* __restrict__ mu,
                         float* __restrict__ out,
                         const int* __restrict__ ei32,
                         const float* __restrict__ Wf2,
                         const float* __restrict__ W1,
                         const float* __restrict__ W2) {
    if (blockIdx.x == 0 && threadIdx.x == 0) {
        int flag = 1;
        #pragma unroll
        for (int i = 0; i < 16; i++)
            if (ei32[2 * i + 1] != 0) flag = 0;
        g_idx64 = flag;
    }
    int i = blockIdx.x * blockDim.x + threadIdx.x;
    if (i < N_NODES) g_hist[i] = 0;
    if (i < HID * H3) {
        g_wf2t[i] = __uint_as_float(f2tf32(Wf2[i]));
        g_w1t[i]  = __uint_as_float(f2tf32(W1[i]));
    }
    if (i < H3 * H3) g_w2t[i] = __uint_as_float(f2tf32(W2[i]));
    const int nq4 = N_NODES * HID / 4;
    const int nm4 = N_NODES * H3 / 4;
    float4* o4 = (float4*)out;
    if (i < nq4)            o4[i] = ((const float4*)q)[i];
    else if (i < nq4 + nm4) o4[i] = ((const float4*)mu)[i - nq4];
}

// --------------------------- counting sort by target -----------------------
__global__ void hist_kernel(const int* __restrict__ ei32,
                            const long long* __restrict__ ei64) {
    int e = blockIdx.x * blockDim.x + threadIdx.x;
    if (e < N_EDGES) {
        int t = g_idx64 ? (int)ei64[e] : ei32[e];
        atomicAdd(&g_hist[t], 1);
    }
}

__global__ __launch_bounds__(1024) void scan_kernel() {
    __shared__ int part[1024];
    const int tid = threadIdx.x;
    const int base = tid * 10;
    int local[10];
    int s = 0;
    #pragma unroll
    for (int j = 0; j < 10; j++) {
        int v = (base + j < N_NODES) ? g_hist[base + j] : 0;
        local[j] = s;
        s += v;
    }
    part[tid] = s;
    __syncthreads();
    const int own = s;
    for (int d = 1; d < 1024; d <<= 1) {
        int v = (tid >= d) ? part[tid - d] : 0;
        __syncthreads();
        part[tid] += v;
        __syncthreads();
    }
    int excl = part[tid] - own;
    #pragma unroll
    for (int j = 0; j < 10; j++)
        if (base + j < N_NODES) g_cursor[base + j] = excl + local[j];
}

__global__ void scatter_kernel(const int* __restrict__ ei32,
                               const long long* __restrict__ ei64) {
    int e = blockIdx.x * blockDim.x + threadIdx.x;
    if (e < N_EDGES) {
        int t = g_idx64 ? (int)ei64[e] : ei32[e];
        int pos = atomicAdd(&g_cursor[t], 1);
        g_perm[pos] = e;
    }
}

// ---------------------------------------------------------------------------
// Kernel 2: node MLP via TF32 MMA (unchanged).
// ---------------------------------------------------------------------------
#define SMEM_NODE 115712
#define QPITCH 132
#define TPITCH 388

__global__ __launch_bounds__(256) void node_mma(const float* __restrict__ q,
                                                const float* __restrict__ b1,
                                                const float* __restrict__ b2) {
    extern __shared__ char smem[];
    uint32_t* qs   = (uint32_t*)smem;
    float*    wbuf = (float*)(smem + 16896);
    uint32_t* t1s  = (uint32_t*)(smem + 66048);

    const int tid = threadIdx.x;
    const int n0 = blockIdx.x * NPB;
    const int F4 = KCH * H3 / 4;  // 1536

    auto stage_slot = [&](int slot) {
        float* dst = wbuf + (slot & 1) * KCH * H3;
        const float4* src = (slot < NCHUNK)
            ? (const float4*)g_w1t + slot * F4
            : (const float4*)g_w2t + (slot - NCHUNK) * F4;
        for (int i = tid; i < F4; i += 256) {
            int kk = i / 96;
            int n  = (i % 96) * 4;
            int ns = n ^ ((kk & 3) << 3);
            cp_async16(dst + kk * H3 + ns, src + i);
        }
        cp_commit();
    };

    stage_slot(0);
    stage_slot(1);

    for (int i = tid; i < NPB * (HID / 4); i += 256) {
        int r = i >> 5;
        int c4 = (i & 31) * 4;
        float4 v = (n0 + r < N_NODES)
            ? __ldg((const float4*)(q + (n0 + r) * HID + c4))
            : make_float4(0.f, 0.f, 0.f, 0.f);
        uint32_t* dst = qs + r * QPITCH + c4;
        dst[0] = f2tf32(v.x); dst[1] = f2tf32(v.y);
        dst[2] = f2tf32(v.z); dst[3] = f2tf32(v.w);
    }

    const int warp = tid >> 5, lane = tid & 31;
    const int g = lane >> 2, c = lane & 3;
    const int C0 = warp * 48;

    float d[2][6][4];
    #pragma unroll
    for (int mt = 0; mt < 2; mt++)
        #pragma unroll
        for (int j = 0; j < 6; j++)
            #pragma unroll
            for (int r = 0; r < 4; r++) d[mt][j][r] = 0.f;

    #pragma unroll
    for (int ch = 0; ch < NCHUNK; ch++) {
        cp_wait<1>();
        __syncthreads();
        const float* wch = wbuf + (ch & 1) * KCH * H3;
        #pragma unroll
        for (int ks = 0; ks < 2; ks++) {
            const int kglob = ch * KCH + 8 * ks;
            uint32_t a[2][4];
            #pragma unroll
            for (int mt = 0; mt < 2; mt++) {
                const uint32_t* ap = qs + (16 * mt + g) * QPITCH + kglob + c;
                a[mt][0] = ap[0];
                a[mt][1] = ap[8 * QPITCH];
                a[mt][2] = ap[4];
                a[mt][3] = ap[8 * QPITCH + 4];
            }
            uint32_t b[6][2];
            #pragma unroll
            for (int j = 0; j < 6; j++) {
                const int n = C0 + 8 * j + g;
                const int kk0 = 8 * ks + c;
                b[j][0] = ((const uint32_t*)wch)[kk0 * H3 + (n ^ ((kk0 & 3) << 3))];
                const int kk1 = kk0 + 4;
                b[j][1] = ((const uint32_t*)wch)[kk1 * H3 + (n ^ ((kk1 & 3) << 3))];
            }
            #pragma unroll
            for (int mt = 0; mt < 2; mt++)
                #pragma unroll
                for (int j = 0; j < 6; j++)
                    mma_tf32(d[mt][j], a[mt], b[j]);
        }
        __syncthreads();
        stage_slot(ch + 2);
    }

    #pragma unroll
    for (int mt = 0; mt < 2; mt++)
        #pragma unroll
        for (int j = 0; j < 6; j++) {
            const int C = C0 + 8 * j + 2 * c;
            const float bb0 = __ldg(&b1[C]), bb1 = __ldg(&b1[C + 1]);
            const int r0 = 16 * mt + g;
            float v0 = silu_f(d[mt][j][0] + bb0);
            float v1 = silu_f(d[mt][j][1] + bb1);
            *(ull*)(t1s + r0 * TPITCH + C) =
                pack2(__uint_as_float(f2tf32(v0)), __uint_as_float(f2tf32(v1)));
            float v2 = silu_f(d[mt][j][2] + bb0);
            float v3 = silu_f(d[mt][j][3] + bb1);
            *(ull*)(t1s + (r0 + 8) * TPITCH + C) =
                pack2(__uint_as_float(f2tf32(v2)), __uint_as_float(f2tf32(v3)));
        }
    #pragma unroll
    for (int mt = 0; mt < 2; mt++)
        #pragma unroll
        for (int j = 0; j < 6; j++)
            #pragma unroll
            for (int r = 0; r < 4; r++) d[mt][j][r] = 0.f;

    const int NCH2 = H3 / KCH;   // 24
    for (int ch = 0; ch < NCH2; ch++) {
        if (ch == NCH2 - 1) cp_wait<0>(); else cp_wait<1>();
        __syncthreads();
        const float* wch = wbuf + (ch & 1) * KCH * H3;
        #pragma unroll
        for (int ks = 0; ks < 2; ks++) {
            const int kglob = ch * KCH + 8 * ks;
            uint32_t a[2][4];
            #pragma unroll
            for (int mt = 0; mt < 2; mt++) {
                const uint32_t* ap = t1s + (16 * mt + g) * TPITCH + kglob + c;
                a[mt][0] = ap[0];
                a[mt][1] = ap[8 * TPITCH];
                a[mt][2] = ap[4];
                a[mt][3] = ap[8 * TPITCH + 4];
            }
            uint32_t b[6][2];
            #pragma unroll
            for (int j = 0; j < 6; j++) {
                const int n = C0 + 8 * j + g;
                const int kk0 = 8 * ks + c;
                b[j][0] = ((const uint32_t*)wch)[kk0 * H3 + (n ^ ((kk0 & 3) << 3))];
                const int kk1 = kk0 + 4;
                b[j][1] = ((const uint32_t*)wch)[kk1 * H3 + (n ^ ((kk1 & 3) << 3))];
            }
            #pragma unroll
            for (int mt = 0; mt < 2; mt++)
                #pragma unroll
                for (int j = 0; j < 6; j++)
                    mma_tf32(d[mt][j], a[mt], b[j]);
        }
        __syncthreads();
        if (ch + 2 < NCH2) stage_slot(NCHUNK + ch + 2);
    }

    #pragma unroll
    for (int mt = 0; mt < 2; mt++)
        #pragma unroll
        for (int j = 0; j < 6; j++) {
            const int C = C0 + 8 * j + 2 * c;
            const float bb0 = __ldg(&b2[C]), bb1 = __ldg(&b2[C + 1]);
            const int r0 = n0 + 16 * mt + g;
            if (r0 < N_NODES)
                *(float2*)(g_x + r0 * H3 + C) =
                    make_float2(d[mt][j][0] + bb0, d[mt][j][1] + bb1);
            if (r0 + 8 < N_NODES)
                *(float2*)(g_x + (r0 + 8) * H3 + C) =
                    make_float2(d[mt][j][2] + bb0, d[mt][j][3] + bb1);
        }
}

// ---------------------------------------------------------------------------
// Kernel 3: fused edge kernel — ALL-MMA, EPB=96, 3-deep staged pipeline.
// 512 threads, 16 warps. Phase B: warp = 3 n8-tiles x 6 m16-tiles, K=128.
// Partial last block masked via cut=0 (zero filters -> zero atomics).
// ---------------------------------------------------------------------------
// smem layout:
//   h1s  [96][132] u32  @ 0       (50688)
//   wbuf [3][16][384]   @ 50688   (73728)
//   Wf1s [24][132]      @ 124416  (12672)   rows 20-23 zeroed
//   rbfs [96][36]       @ 137088  (13824)   cols 20-35 zeroed, physical rows
//   bf1s [HID]          @ 150912  (512)
//   bf2s [H3]           @ 151424  (1536)
//   cuts [96]           @ 152960  (384)
//   uvs  [96*3]         @ 153344  (1152)
//   srcs [96] int       @ 154496  (384)
//   tgts [96] int       @ 154880  (384)
//   es   [96] int       @ 155264  (384)
#define SMEM_EDGE 155648
#define H1PITCH 132
#define WF1PITCH 132
#define RBFPITCH 36

__global__ __launch_bounds__(EK_THREADS) void edge_kernel(
        const int* __restrict__ ei32, const long long* __restrict__ ei64,
        const float* __restrict__ rbf, const float* __restrict__ uv,
        const float* __restrict__ cut,
        const float* __restrict__ Wf1, const float* __restrict__ bf1,
        const float* __restrict__ bf2,
        const float* __restrict__ mu, float* __restrict__ out) {
    extern __shared__ char smem[];
    uint32_t* h1u  = (uint32_t*)smem;
    float*    wbuf = (float*)(smem + 50688);
    float*    Wf1s = (float*)(smem + 124416);
    float*    rbfs = (float*)(smem + 137088);
    float*    bf1s = (float*)(smem + 150912);
    float*    bf2s = (float*)(smem + 151424);
    float*    cuts = (float*)(smem + 152960);
    float*    uvs  = (float*)(smem + 153344);
    int*      srcs = (int*)(smem + 154496);
    int*      tgts = (int*)(smem + 154880);
    int*      es   = (int*)(smem + 155264);

    const int tid = threadIdx.x;
    const int e0 = blockIdx.x * EPB;
    const int F4 = KCH * H3 / 4;  // 1536

    auto stage_chunk = [&](int chunk) {
        float* dst = wbuf + (chunk % NWBUF) * KCH * H3;
        const float4* src = (const float4*)g_wf2t + chunk * F4;
        for (int i = tid; i < F4; i += EK_THREADS) {
            int kk = i / 96;
            int n  = (i % 96) * 4;
            int ns = n ^ ((kk & 3) << 3);
            cp_async16(dst + kk * H3 + ns, src + i);
        }
        cp_commit();
    };

    stage_chunk(0);
    stage_chunk(1);
    stage_chunk(2);

    if (tid < EPB) {
        int ei = e0 + tid;
        es[tid] = g_perm[(ei < N_EDGES) ? ei : (N_EDGES - 1)];
    }
    // Wf1 -> smem pitch 132 (tf32), rows 20-23 zero
    for (int i = tid; i < NRBF * HID; i += EK_THREADS) {
        int k = i >> 7, j = i & 127;
        ((uint32_t*)Wf1s)[k * WF1PITCH + j] = f2tf32(Wf1[i]);
    }
    for (int i = tid; i < 4 * WF1PITCH; i += EK_THREADS)
        Wf1s[NRBF * WF1PITCH + i] = 0.f;
    // zero rbf pad cols 20-35
    for (int i = tid; i < EPB * 4; i += EK_THREADS) {
        int R = i >> 2;
        *(float4*)(rbfs + R * RBFPITCH + 20 + (i & 3) * 4) =
            make_float4(0.f, 0.f, 0.f, 0.f);
    }
    for (int i = tid; i < H3; i += EK_THREADS) bf2s[i] = bf2[i];
    if (tid < HID) bf1s[tid] = bf1[tid];
    __syncthreads();  // es visible

    // per-edge gathers; rbf by PHYSICAL mma row (tf32), rest by sorted order
    {
        const float4* rsrc = (const float4*)rbf;
        for (int i = tid; i < EPB * 5; i += EK_THREADS) {
            int R = i / 5;
            int e = es[sorted_of_row(R)];
            float4 v = __ldg(rsrc + e * 5 + (i % 5));
            uint32_t* dst = (uint32_t*)(rbfs + R * RBFPITCH + (i % 5) * 4);
            dst[0] = f2tf32(v.x); dst[1] = f2tf32(v.y);
            dst[2] = f2tf32(v.z); dst[3] = f2tf32(v.w);
        }
        for (int i = tid; i < EPB * 3; i += EK_THREADS) {
            int e = es[i / 3];
            uvs[i] = uv[e * 3 + (i % 3)];
        }
        if (tid < EPB) {
            int e = es[tid];
            const bool valid = (e0 + tid) < N_EDGES;
            cuts[tid] = valid ? cut[e] : 0.f;   // mask dup edges with 0 filter
            if (g_idx64) { tgts[tid] = (int)ei64[e]; srcs[tid] = (int)ei64[N_EDGES + e]; }
            else         { tgts[tid] = ei32[e];      srcs[tid] = ei32[N_EDGES + e]; }
        }
    }
    __syncthreads();

    const int warp = tid >> 5, lane = tid & 31;
    const int g = lane >> 2, c = lane & 3;

    // Phase A via MMA: h1[96,128] = silu(rbf@Wf1 + bf1), K=24 (3 k-steps).
    // Warps 0-11: mt_a = warp>>1 (6 m16 tiles), jbase = (warp&1)*8, 8 n8 tiles.
    if (warp < 12) {
        const int mt_a = warp >> 1;
        const int jbase = (warp & 1) * 8;
        float da[8][4];
        #pragma unroll
        for (int jt = 0; jt < 8; jt++)
            #pragma unroll
            for (int r = 0; r < 4; r++) da[jt][r] = 0.f;

        #pragma unroll
        for (int ks = 0; ks < 3; ks++) {
            uint32_t a[4];
            const uint32_t* ap = (const uint32_t*)rbfs
                                 + (16 * mt_a + g) * RBFPITCH + 8 * ks + c;
            a[0] = ap[0];
            a[1] = ap[8 * RBFPITCH];
            a[2] = ap[4];
            a[3] = ap[8 * RBFPITCH + 4];
            #pragma unroll
            for (int jt = 0; jt < 8; jt++) {
                const int j = jbase + jt;
                uint32_t b[2];
                b[0] = ((const uint32_t*)Wf1s)[(8 * ks + c) * WF1PITCH + 8 * j + g];
                b[1] = ((const uint32_t*)Wf1s)[(8 * ks + c + 4) * WF1PITCH + 8 * j + g];
                mma_tf32(da[jt], a, b);
            }
        }
        const int r0 = 16 * mt_a + g;
        #pragma unroll
        for (int jt = 0; jt < 8; jt++) {
            const int col = 8 * (jbase + jt) + 2 * c;
            const float bb0 = bf1s[col], bb1 = bf1s[col + 1];
            float v0 = silu_f(da[jt][0] + bb0);
            float v1 = silu_f(da[jt][1] + bb1);
            *(ull*)(h1u + r0 * H1PITCH + col) =
                pack2(__uint_as_float(f2tf32(v0)), __uint_as_float(f2tf32(v1)));
            float v2 = silu_f(da[jt][2] + bb0);
            float v3 = silu_f(da[jt][3] + bb1);
            *(ull*)(h1u + (r0 + 8) * H1PITCH + col) =
                pack2(__uint_as_float(f2tf32(v2)), __uint_as_float(f2tf32(v3)));
        }
    }

    // Phase B: main TF32 MMA. warp owns cols [warp*24, warp*24+24) = 3 n8,
    // all 6 m16 tiles (96 edges). a-frags loaded per-mt to cap registers.
    const int C0 = warp * 24;

    float d[6][3][4];
    #pragma unroll
    for (int mt = 0; mt < 6; mt++)
        #pragma unroll
        for (int j = 0; j < 3; j++)
            #pragma unroll
            for (int r = 0; r < 4; r++) d[mt][j][r] = 0.f;

    #pragma unroll
    for (int chunk = 0; chunk < NCHUNK; chunk++) {
        // 3-deep pipeline: keep up to 2 outstanding groups beyond current
        if (chunk < NCHUNK - 2)      cp_wait<2>();
        else if (chunk == NCHUNK - 2) cp_wait<1>();
        else                          cp_wait<0>();
        __syncthreads();   // chunk ready; for chunk 0 also orders h1 writes
        const float* wch = wbuf + (chunk % NWBUF) * KCH * H3;
        #pragma unroll
        for (int ks = 0; ks < 2; ks++) {
            const int kglob = chunk * KCH + 8 * ks;
            uint32_t b[3][2];
            #pragma unroll
            for (int j = 0; j < 3; j++) {
                const int n = C0 + 8 * j + g;
                const int kk0 = 8 * ks + c;
                b[j][0] = ((const uint32_t*)wch)[kk0 * H3 + (n ^ ((kk0 & 3) << 3))];
                const int kk1 = kk0 + 4;
                b[j][1] = ((const uint32_t*)wch)[kk1 * H3 + (n ^ ((kk1 & 3) << 3))];
            }
            #pragma unroll
            for (int mt = 0; mt < 6; mt++) {
                uint32_t a[4];
                const uint32_t* hp = h1u + (16 * mt + g) * H1PITCH + kglob + c;
                a[0] = hp[0];
                a[1] = hp[8 * H1PITCH];
                a[2] = hp[4];
                a[3] = hp[8 * H1PITCH + 4];
                #pragma unroll
                for (int j = 0; j < 3; j++)
                    mma_tf32(d[mt][j], a, b[j]);
            }
        }
        __syncthreads();
        if (chunk + NWBUF < NCHUNK) stage_chunk(chunk + NWBUF);
    }

    // Phase C: epilogue, j-outer, run-combined scatter.
    // Lane owns sorted edges s = 12g+idx, idx 0..11;
    // physical row R = 16*(idx>>1) + 8*(idx&1) + g.
    float* outq  = out;
    float* outmu = out + N_NODES * HID;

    #pragma unroll
    for (int j = 0; j < 3; j++) {
        const int C = C0 + 8 * j + 2 * c;
        const int part = C >> 7, jj = C & 127;
        const float b0 = bf2s[C], b1v = bf2s[C + 1];
        float a0 = 0.f, a1 = 0.f;
        float v[3][2] = {{0.f,0.f},{0.f,0.f},{0.f,0.f}};

        #pragma unroll
        for (int idx = 0; idx < 12; idx++) {
            const int s = 12 * g + idx;
            const int mt = idx >> 1, h = idx & 1;
            const float cs = cuts[s];
            const int src = srcs[s], tgt = tgts[s];
            const float* xb = g_x + src * H3;
            float f0 = (d[mt][j][2 * h]     + b0)  * cs;
            float f1 = (d[mt][j][2 * h + 1] + b1v) * cs;

            if (part == 0) {
                float2 x2 = __ldg((const float2*)(xb + jj));
                a0 += x2.x * f0;
                a1 += x2.y * f1;
            } else if (part == 1) {
                float2 x2 = __ldg((const float2*)(xb + HID + jj));
                float t0 = x2.x * f0, t1 = x2.y * f1;
                #pragma unroll
                for (int dd = 0; dd < 3; dd++) {
                    float u = uvs[s * 3 + dd];
                    v[dd][0] += u * t0;
                    v[dd][1] += u * t1;
                }
            } else {
                float2 x2 = __ldg((const float2*)(xb + 2 * HID + jj));
                float t0 = x2.x * f0, t1 = x2.y * f1;
                #pragma unroll
                for (int dd = 0; dd < 3; dd++) {
                    float2 m2 = __ldg((const float2*)(mu + (src * 3 + dd) * HID + jj));
                    v[dd][0] += m2.x * t0;
                    v[dd][1] += m2.y * t1;
                }
            }

            const bool flush = (idx == 11) || (tgts[s + 1] != tgt);
            if (flush) {
                if (part == 0) {
                    red_add_v2(outq + tgt * HID + jj, a0, a1);
                    a0 = 0.f; a1 = 0.f;
                } else {
                    #pragma unroll
                    for (int dd = 0; dd < 3; dd++) {
                        red_add_v2(outmu + (tgt * 3 + dd) * HID + jj, v[dd][0], v[dd][1]);
                        v[dd][0] = 0.f; v[dd][1] = 0.f;
                    }
                }
            }
        }
    }
}

extern "C" void kernel_launch(void* const* d_in, const int* in_sizes, int n_in,
                              void* d_out, int out_size) {
    const float* q   = (const float*)d_in[0];
    const float* mu  = (const float*)d_in[1];
    const void*  ei  = d_in[2];
    const float* rbf = (const float*)d_in[3];
    const float* uvp = (const float*)d_in[4];
    const float* cut = (const float*)d_in[5];
    const float* W1  = (const float*)d_in[6];
    const float* b1  = (const float*)d_in[7];
    const float* W2  = (const float*)d_in[8];
    const float* b2  = (const float*)d_in[9];
    const float* Wf1 = (const float*)d_in[10];
    const float* bf1 = (const float*)d_in[11];
    const float* Wf2 = (const float*)d_in[12];
    const float* bf2 = (const float*)d_in[13];
    float* out = (float*)d_out;

    cudaFuncSetAttribute(edge_kernel,
                         cudaFuncAttributeMaxDynamicSharedMemorySize, SMEM_EDGE);
    cudaFuncSetAttribute(node_mma,
                         cudaFuncAttributeMaxDynamicSharedMemorySize, SMEM_NODE);

    const int total4 = N_NODES * (HID + H3) / 4;
    init_out<<<(total4 + 255) / 256, 256>>>(q, mu, out, (const int*)ei, Wf2, W1, W2);
    hist_kernel<<<(N_EDGES + 255) / 256, 256>>>((const int*)ei, (const long long*)ei);
    scan_kernel<<<1, 1024>>>();
    scatter_kernel<<<(N_EDGES + 255) / 256, 256>>>((const int*)ei, (const long long*)ei);
    node_mma<<<(N_NODES + NPB - 1) / NPB, 256, SMEM_NODE>>>(q, b1, b2);
    edge_kernel<<<(N_EDGES + EPB - 1) / EPB, EK_THREADS, SMEM_EDGE>>>(
        (const int*)ei, (const long long*)ei,
        rbf, uvp, cut, Wf1, bf1, bf2, mu, out);
}

// round 14
// speedup vs baseline: 1.0012x; 1.0012x over previous
#include <cuda_runtime.h>
#include <stdint.h>

#define N_NODES 10000
#define N_EDGES 320000
#define HID 128
#define H3 384
#define NRBF 20
#define EPB 96      // edges per block (edge kernel): 6 m16-tiles
#define NPB 32      // nodes per block (node kernel)
#define KCH 16      // weight k-rows per staged chunk
#define NCHUNK (HID / KCH)   // 8
#define EK_THREADS 512
#define NWBUF 3     // staging buffers (3-deep pipeline)

typedef unsigned long long ull;

// scratch
__device__ float g_x[N_NODES * H3];     // node MLP output [N, 384]
__device__ float g_wf2t[HID * H3];      // Wf2 as tf32 bits
__device__ float g_w1t[HID * H3];       // W1 as tf32 bits
__device__ float g_w2t[H3 * H3];        // W2 as tf32 bits
__device__ int g_idx64;
__device__ int g_hist[N_NODES];
__device__ int g_cursor[N_NODES];
__device__ int g_perm[N_EDGES];         // edge ids sorted by target

__device__ __forceinline__ float silu_f(float v) {
    return v / (1.0f + __expf(-v));
}
__device__ __forceinline__ ull pack2(float lo, float hi) {
    ull r;
    asm("mov.b64 %0,{%1,%2};" : "=l"(r) : "f"(lo), "f"(hi));
    return r;
}
__device__ __forceinline__ uint32_t f2tf32(float f) {
    uint32_t r;
    asm("cvt.rna.tf32.f32 %0,%1;" : "=r"(r) : "f"(f));
    return r;
}
__device__ __forceinline__ void mma_tf32(float* d, const uint32_t* a, const uint32_t* b) {
    asm("mma.sync.aligned.m16n8k8.row.col.f32.tf32.tf32.f32 "
        "{%0,%1,%2,%3},{%4,%5,%6,%7},{%8,%9},{%0,%1,%2,%3};"
        : "+f"(d[0]), "+f"(d[1]), "+f"(d[2]), "+f"(d[3])
        : "r"(a[0]), "r"(a[1]), "r"(a[2]), "r"(a[3]), "r"(b[0]), "r"(b[1]));
}
__device__ __forceinline__ void red_add_v2(float* p, float a, float b) {
    asm volatile("red.global.add.v2.f32 [%0],{%1,%2};"
                 :: "l"(p), "f"(a), "f"(b) : "memory");
}
__device__ __forceinline__ void cp_async16(void* sdst, const void* gsrc) {
    unsigned s = (unsigned)__cvta_generic_to_shared(sdst);
    asm volatile("cp.async.cg.shared.global [%0],[%1],16;" :: "r"(s), "l"(gsrc));
}
__device__ __forceinline__ void cp_commit() {
    asm volatile("cp.async.commit_group;");
}
template <int N>
__device__ __forceinline__ void cp_wait() {
    asm volatile("cp.async.wait_group %0;" :: "n"(N));
}

// sorted position s for physical MMA row R (bijection on [0,96))
// R = 16*mt + 8*half + g  <->  s = 12*g + 2*mt + half
__device__ __forceinline__ int sorted_of_row(int R) {
    return 12 * (R & 7) + ((R >> 4) << 1) + ((R >> 3) & 1);
}

// ---------------------------------------------------------------------------
// Kernel 1: out = concat(q, mu); idx dtype; zero hist; tf32-convert weights.
// ---------------------------------------------------------------------------
__global__ void init_out(const float* __restrict__ q,
                         const float* __restrict__ mu,
                         float* __restrict__ out,
                         const int* __restrict__ ei32,
                         const float* __restrict__ Wf2,
                         const float* __restrict__ W1,
                         const float* __restrict__ W2) {
    if (blockIdx.x == 0 && threadIdx.x == 0) {
        int flag = 1;
        #pragma unroll
        for (int i = 0; i < 16; i++)
            if (ei32[2 * i + 1] != 0) flag = 0;
        g_idx64 = flag;
    }
    int i = blockIdx.x * blockDim.x + threadIdx.x;
    if (i < N_NODES) g_hist[i] = 0;
    if (i < HID * H3) {
        g_wf2t[i] = __uint_as_float(f2tf32(Wf2[i]));
        g_w1t[i]  = __uint_as_float(f2tf32(W1[i]));
    }
    if (i < H3 * H3) g_w2t[i] = __uint_as_float(f2tf32(W2[i]));
    const int nq4 = N_NODES * HID / 4;
    const int nm4 = N_NODES * H3 / 4;
    float4* o4 = (float4*)out;
    if (i < nq4)            o4[i] = ((const float4*)q)[i];
    else if (i < nq4 + nm4) o4[i] = ((const float4*)mu)[i - nq4];
}

// --------------------------- counting sort by target -----------------------
__global__ void hist_kernel(const int* __restrict__ ei32,
                            const long long* __restrict__ ei64) {
    int e = blockIdx.x * blockDim.x + threadIdx.x;
    if (e < N_EDGES) {
        int t = g_idx64 ? (int)ei64[e] : ei32[e];
        atomicAdd(&g_hist[t], 1);
    }
}

__global__ __launch_bounds__(1024) void scan_kernel() {
    __shared__ int part[1024];
    const int tid = threadIdx.x;
    const int base = tid * 10;
    int local[10];
    int s = 0;
    #pragma unroll
    for (int j = 0; j < 10; j++) {
        int v = (base + j < N_NODES) ? g_hist[base + j] : 0;
        local[j] = s;
        s += v;
    }
    part[tid] = s;
    __syncthreads();
    const int own = s;
    for (int d = 1; d < 1024; d <<= 1) {
        int v = (tid >= d) ? part[tid - d] : 0;
        __syncthreads();
        part[tid] += v;
        __syncthreads();
    }
    int excl = part[tid] - own;
    #pragma unroll
    for (int j = 0; j < 10; j++)
        if (base + j < N_NODES) g_cursor[base + j] = excl + local[j];
}

__global__ void scatter_kernel(const int* __restrict__ ei32,
                               const long long* __restrict__ ei64) {
    int e = blockIdx.x * blockDim.x + threadIdx.x;
    if (e < N_EDGES) {
        int t = g_idx64 ? (int)ei64[e] : ei32[e];
        int pos = atomicAdd(&g_cursor[t], 1);
        g_perm[pos] = e;
    }
}

// ---------------------------------------------------------------------------
// Kernel 2: node MLP via TF32 MMA (unchanged).
// ---------------------------------------------------------------------------
#define SMEM_NODE 115712
#define QPITCH 132
#define TPITCH 388

__global__ __launch_bounds__(256) void node_mma(const float* __restrict__ q,
                                                const float* __restrict__ b1,
                                                const float* __restrict__ b2) {
    extern __shared__ char smem[];
    uint32_t* qs   = (uint32_t*)smem;
    float*    wbuf = (float*)(smem + 16896);
    uint32_t* t1s  = (uint32_t*)(smem + 66048);

    const int tid = threadIdx.x;
    const int n0 = blockIdx.x * NPB;
    const int F4 = KCH * H3 / 4;  // 1536

    auto stage_slot = [&](int slot) {
        float* dst = wbuf + (slot & 1) * KCH * H3;
        const float4* src = (slot < NCHUNK)
            ? (const float4*)g_w1t + slot * F4
            : (const float4*)g_w2t + (slot - NCHUNK) * F4;
        for (int i = tid; i < F4; i += 256) {
            int kk = i / 96;
            int n  = (i % 96) * 4;
            int ns = n ^ ((kk & 3) << 3);
            cp_async16(dst + kk * H3 + ns, src + i);
        }
        cp_commit();
    };

    stage_slot(0);
    stage_slot(1);

    for (int i = tid; i < NPB * (HID / 4); i += 256) {
        int r = i >> 5;
        int c4 = (i & 31) * 4;
        float4 v = (n0 + r < N_NODES)
            ? __ldg((const float4*)(q + (n0 + r) * HID + c4))
            : make_float4(0.f, 0.f, 0.f, 0.f);
        uint32_t* dst = qs + r * QPITCH + c4;
        dst[0] = f2tf32(v.x); dst[1] = f2tf32(v.y);
        dst[2] = f2tf32(v.z); dst[3] = f2tf32(v.w);
    }

    const int warp = tid >> 5, lane = tid & 31;
    const int g = lane >> 2, c = lane & 3;
    const int C0 = warp * 48;

    float d[2][6][4];
    #pragma unroll
    for (int mt = 0; mt < 2; mt++)
        #pragma unroll
        for (int j = 0; j < 6; j++)
            #pragma unroll
            for (int r = 0; r < 4; r++) d[mt][j][r] = 0.f;

    #pragma unroll
    for (int ch = 0; ch < NCHUNK; ch++) {
        cp_wait<1>();
        __syncthreads();
        const float* wch = wbuf + (ch & 1) * KCH * H3;
        #pragma unroll
        for (int ks = 0; ks < 2; ks++) {
            const int kglob = ch * KCH + 8 * ks;
            uint32_t a[2][4];
            #pragma unroll
            for (int mt = 0; mt < 2; mt++) {
                const uint32_t* ap = qs + (16 * mt + g) * QPITCH + kglob + c;
                a[mt][0] = ap[0];
                a[mt][1] = ap[8 * QPITCH];
                a[mt][2] = ap[4];
                a[mt][3] = ap[8 * QPITCH + 4];
            }
            uint32_t b[6][2];
            #pragma unroll
            for (int j = 0; j < 6; j++) {
                const int n = C0 + 8 * j + g;
                const int kk0 = 8 * ks + c;
                b[j][0] = ((const uint32_t*)wch)[kk0 * H3 + (n ^ ((kk0 & 3) << 3))];
                const int kk1 = kk0 + 4;
                b[j][1] = ((const uint32_t*)wch)[kk1 * H3 + (n ^ ((kk1 & 3) << 3))];
            }
            #pragma unroll
            for (int mt = 0; mt < 2; mt++)
                #pragma unroll
                for (int j = 0; j < 6; j++)
                    mma_tf32(d[mt][j], a[mt], b[j]);
        }
        __syncthreads();
        stage_slot(ch + 2);
    }

    #pragma unroll
    for (int mt = 0; mt < 2; mt++)
        #pragma unroll
        for (int j = 0; j < 6; j++) {
            const int C = C0 + 8 * j + 2 * c;
            const float bb0 = __ldg(&b1[C]), bb1 = __ldg(&b1[C + 1]);
            const int r0 = 16 * mt + g;
            float v0 = silu_f(d[mt][j][0] + bb0);
            float v1 = silu_f(d[mt][j][1] + bb1);
            *(ull*)(t1s + r0 * TPITCH + C) =
                pack2(__uint_as_float(f2tf32(v0)), __uint_as_float(f2tf32(v1)));
            float v2 = silu_f(d[mt][j][2] + bb0);
            float v3 = silu_f(d[mt][j][3] + bb1);
            *(ull*)(t1s + (r0 + 8) * TPITCH + C) =
                pack2(__uint_as_float(f2tf32(v2)), __uint_as_float(f2tf32(v3)));
        }
    #pragma unroll
    for (int mt = 0; mt < 2; mt++)
        #pragma unroll
        for (int j = 0; j < 6; j++)
            #pragma unroll
            for (int r = 0; r < 4; r++) d[mt][j][r] = 0.f;

    const int NCH2 = H3 / KCH;   // 24
    for (int ch = 0; ch < NCH2; ch++) {
        if (ch == NCH2 - 1) cp_wait<0>(); else cp_wait<1>();
        __syncthreads();
        const float* wch = wbuf + (ch & 1) * KCH * H3;
        #pragma unroll
        for (int ks = 0; ks < 2; ks++) {
            const int kglob = ch * KCH + 8 * ks;
            uint32_t a[2][4];
            #pragma unroll
            for (int mt = 0; mt < 2; mt++) {
                const uint32_t* ap = t1s + (16 * mt + g) * TPITCH + kglob + c;
                a[mt][0] = ap[0];
                a[mt][1] = ap[8 * TPITCH];
                a[mt][2] = ap[4];
                a[mt][3] = ap[8 * TPITCH + 4];
            }
            uint32_t b[6][2];
            #pragma unroll
            for (int j = 0; j < 6; j++) {
                const int n = C0 + 8 * j + g;
                const int kk0 = 8 * ks + c;
                b[j][0] = ((const uint32_t*)wch)[kk0 * H3 + (n ^ ((kk0 & 3) << 3))];
                const int kk1 = kk0 + 4;
                b[j][1] = ((const uint32_t*)wch)[kk1 * H3 + (n ^ ((kk1 & 3) << 3))];
            }
            #pragma unroll
            for (int mt = 0; mt < 2; mt++)
                #pragma unroll
                for (int j = 0; j < 6; j++)
                    mma_tf32(d[mt][j], a[mt], b[j]);
        }
        __syncthreads();
        if (ch + 2 < NCH2) stage_slot(NCHUNK + ch + 2);
    }

    #pragma unroll
    for (int mt = 0; mt < 2; mt++)
        #pragma unroll
        for (int j = 0; j < 6; j++) {
            const int C = C0 + 8 * j + 2 * c;
            const float bb0 = __ldg(&b2[C]), bb1 = __ldg(&b2[C + 1]);
            const int r0 = n0 + 16 * mt + g;
            if (r0 < N_NODES)
                *(float2*)(g_x + r0 * H3 + C) =
                    make_float2(d[mt][j][0] + bb0, d[mt][j][1] + bb1);
            if (r0 + 8 < N_NODES)
                *(float2*)(g_x + (r0 + 8) * H3 + C) =
                    make_float2(d[mt][j][2] + bb0, d[mt][j][3] + bb1);
        }
}

// ---------------------------------------------------------------------------
// Kernel 3: fused edge kernel — ALL-MMA, EPB=96, 3-deep staged pipeline.
// 512 threads, 16 warps. Phase B: warp = 3 n8-tiles x 6 m16-tiles, K=128.
// Partial last block masked via cut=0 (zero filters -> zero atomics).
// ---------------------------------------------------------------------------
// smem layout:
//   h1s  [96][132] u32  @ 0       (50688)
//   wbuf [3][16][384]   @ 50688   (73728)
//   Wf1s [24][132]      @ 124416  (12672)   rows 20-23 zeroed
//   rbfs [96][36]       @ 137088  (13824)   cols 20-35 zeroed, physical rows
//   bf1s [HID]          @ 150912  (512)
//   bf2s [H3]           @ 151424  (1536)
//   cuts [96]           @ 152960  (384)
//   uvs  [96*3]         @ 153344  (1152)
//   srcs [96] int       @ 154496  (384)
//   tgts [96] int       @ 154880  (384)
//   es   [96] int       @ 155264  (384)
#define SMEM_EDGE 155648
#define H1PITCH 132
#define WF1PITCH 132
#define RBFPITCH 36

__global__ __launch_bounds__(EK_THREADS) void edge_kernel(
        const int* __restrict__ ei32, const long long* __restrict__ ei64,
        const float* __restrict__ rbf, const float* __restrict__ uv,
        const float* __restrict__ cut,
        const float* __restrict__ Wf1, const float* __restrict__ bf1,
        const float* __restrict__ bf2,
        const float* __restrict__ mu, float* __restrict__ out) {
    extern __shared__ char smem[];
    uint32_t* h1u  = (uint32_t*)smem;
    float*    wbuf = (float*)(smem + 50688);
    float*    Wf1s = (float*)(smem + 124416);
    float*    rbfs = (float*)(smem + 137088);
    float*    bf1s = (float*)(smem + 150912);
    float*    bf2s = (float*)(smem + 151424);
    float*    cuts = (float*)(smem + 152960);
    float*    uvs  = (float*)(smem + 153344);
    int*      srcs = (int*)(smem + 154496);
    int*      tgts = (int*)(smem + 154880);
    int*      es   = (int*)(smem + 155264);

    const int tid = threadIdx.x;
    const int e0 = blockIdx.x * EPB;
    const int F4 = KCH * H3 / 4;  // 1536

    auto stage_chunk = [&](int chunk) {
        float* dst = wbuf + (chunk % NWBUF) * KCH * H3;
        const float4* src = (const float4*)g_wf2t + chunk * F4;
        for (int i = tid; i < F4; i += EK_THREADS) {
            int kk = i / 96;
            int n  = (i % 96) * 4;
            int ns = n ^ ((kk & 3) << 3);
            cp_async16(dst + kk * H3 + ns, src + i);
        }
        cp_commit();
    };

    stage_chunk(0);
    stage_chunk(1);
    stage_chunk(2);

    if (tid < EPB) {
        int ei = e0 + tid;
        es[tid] = g_perm[(ei < N_EDGES) ? ei : (N_EDGES - 1)];
    }
    // Wf1 -> smem pitch 132 (tf32), rows 20-23 zero
    for (int i = tid; i < NRBF * HID; i += EK_THREADS) {
        int k = i >> 7, j = i & 127;
        ((uint32_t*)Wf1s)[k * WF1PITCH + j] = f2tf32(Wf1[i]);
    }
    for (int i = tid; i < 4 * WF1PITCH; i += EK_THREADS)
        Wf1s[NRBF * WF1PITCH + i] = 0.f;
    // zero rbf pad cols 20-35
    for (int i = tid; i < EPB * 4; i += EK_THREADS) {
        int R = i >> 2;
        *(float4*)(rbfs + R * RBFPITCH + 20 + (i & 3) * 4) =
            make_float4(0.f, 0.f, 0.f, 0.f);
    }
    for (int i = tid; i < H3; i += EK_THREADS) bf2s[i] = bf2[i];
    if (tid < HID) bf1s[tid] = bf1[tid];
    __syncthreads();  // es visible

    // per-edge gathers; rbf by PHYSICAL mma row (tf32), rest by sorted order
    {
        const float4* rsrc = (const float4*)rbf;
        for (int i = tid; i < EPB * 5; i += EK_THREADS) {
            int R = i / 5;
            int e = es[sorted_of_row(R)];
            float4 v = __ldg(rsrc + e * 5 + (i % 5));
            uint32_t* dst = (uint32_t*)(rbfs + R * RBFPITCH + (i % 5) * 4);
            dst[0] = f2tf32(v.x); dst[1] = f2tf32(v.y);
            dst[2] = f2tf32(v.z); dst[3] = f2tf32(v.w);
        }
        for (int i = tid; i < EPB * 3; i += EK_THREADS) {
            int e = es[i / 3];
            uvs[i] = uv[e * 3 + (i % 3)];
        }
        if (tid < EPB) {
            int e = es[tid];
            const bool valid = (e0 + tid) < N_EDGES;
            cuts[tid] = valid ? cut[e] : 0.f;   // mask dup edges with 0 filter
            if (g_idx64) { tgts[tid] = (int)ei64[e]; srcs[tid] = (int)ei64[N_EDGES + e]; }
            else         { tgts[tid] = ei32[e];      srcs[tid] = ei32[N_EDGES + e]; }
        }
    }
    __syncthreads();

    const int warp = tid >> 5, lane = tid & 31;
    const int g = lane >> 2, c = lane & 3;

    // Phase A via MMA: h1[96,128] = silu(rbf@Wf1 + bf1), K=24 (3 k-steps).
    // Warps 0-11: mt_a = warp>>1 (6 m16 tiles), jbase = (warp&1)*8, 8 n8 tiles.
    if (warp < 12) {
        const int mt_a = warp >> 1;
        const int jbase = (warp & 1) * 8;
        float da[8][4];
        #pragma unroll
        for (int jt = 0; jt < 8; jt++)
            #pragma unroll
            for (int r = 0; r < 4; r++) da[jt][r] = 0.f;

        #pragma unroll
        for (int ks = 0; ks < 3; ks++) {
            uint32_t a[4];
            const uint32_t* ap = (const uint32_t*)rbfs
                                 + (16 * mt_a + g) * RBFPITCH + 8 * ks + c;
            a[0] = ap[0];
            a[1] = ap[8 * RBFPITCH];
            a[2] = ap[4];
            a[3] = ap[8 * RBFPITCH + 4];
            #pragma unroll
            for (int jt = 0; jt < 8; jt++) {
                const int j = jbase + jt;
                uint32_t b[2];
                b[0] = ((const uint32_t*)Wf1s)[(8 * ks + c) * WF1PITCH + 8 * j + g];
                b[1] = ((const uint32_t*)Wf1s)[(8 * ks + c + 4) * WF1PITCH + 8 * j + g];
                mma_tf32(da[jt], a, b);
            }
        }
        const int r0 = 16 * mt_a + g;
        #pragma unroll
        for (int jt = 0; jt < 8; jt++) {
            const int col = 8 * (jbase + jt) + 2 * c;
            const float bb0 = bf1s[col], bb1 = bf1s[col + 1];
            float v0 = silu_f(da[jt][0] + bb0);
            float v1 = silu_f(da[jt][1] + bb1);
            *(ull*)(h1u + r0 * H1PITCH + col) =
                pack2(__uint_as_float(f2tf32(v0)), __uint_as_float(f2tf32(v1)));
            float v2 = silu_f(da[jt][2] + bb0);
            float v3 = silu_f(da[jt][3] + bb1);
            *(ull*)(h1u + (r0 + 8) * H1PITCH + col) =
                pack2(__uint_as_float(f2tf32(v2)), __uint_as_float(f2tf32(v3)));
        }
    }

    // Phase B: main TF32 MMA. warp owns cols [warp*24, warp*24+24) = 3 n8,
    // all 6 m16 tiles (96 edges). a-frags loaded per-mt to cap registers.
    const int C0 = warp * 24;

    float d[6][3][4];
    #pragma unroll
    for (int mt = 0; mt < 6; mt++)
        #pragma unroll
        for (int j = 0; j < 3; j++)
            #pragma unroll
            for (int r = 0; r < 4; r++) d[mt][j][r] = 0.f;

    #pragma unroll
    for (int chunk = 0; chunk < NCHUNK; chunk++) {
        // 3-deep pipeline: keep up to 2 outstanding groups beyond current
        if (chunk < NCHUNK - 2)      cp_wait<2>();
        else if (chunk == NCHUNK - 2) cp_wait<1>();
        else                          cp_wait<0>();
        __syncthreads();   // chunk ready; for chunk 0 also orders h1 writes
        const float* wch = wbuf + (chunk % NWBUF) * KCH * H3;
        #pragma unroll
        for (int ks = 0; ks < 2; ks++) {
            const int kglob = chunk * KCH + 8 * ks;
            uint32_t b[3][2];
            #pragma unroll
            for (int j = 0; j < 3; j++) {
                const int n = C0 + 8 * j + g;
                const int kk0 = 8 * ks + c;
                b[j][0] = ((const uint32_t*)wch)[kk0 * H3 + (n ^ ((kk0 & 3) << 3))];
                const int kk1 = kk0 + 4;
                b[j][1] = ((const uint32_t*)wch)[kk1 * H3 + (n ^ ((kk1 & 3) << 3))];
            }
            #pragma unroll
            for (int mt = 0; mt < 6; mt++) {
                uint32_t a[4];
                const uint32_t* hp = h1u + (16 * mt + g) * H1PITCH + kglob + c;
                a[0] = hp[0];
                a[1] = hp[8 * H1PITCH];
                a[2] = hp[4];
                a[3] = hp[8 * H1PITCH + 4];
                #pragma unroll
                for (int j = 0; j < 3; j++)
                    mma_tf32(d[mt][j], a, b[j]);
            }
        }
        __syncthreads();
        if (chunk + NWBUF < NCHUNK) stage_chunk(chunk + NWBUF);
    }

    // Phase C: epilogue, j-outer, run-combined scatter.
    // Lane owns sorted edges s = 12g+idx, idx 0..11;
    // physical row R = 16*(idx>>1) + 8*(idx&1) + g.
    float* outq  = out;
    float* outmu = out + N_NODES * HID;

    #pragma unroll
    for (int j = 0; j < 3; j++) {
        const int C = C0 + 8 * j + 2 * c;
        const int part = C >> 7, jj = C & 127;
        const float b0 = bf2s[C], b1v = bf2s[C + 1];
        float a0 = 0.f, a1 = 0.f;
        float v[3][2] = {{0.f,0.f},{0.f,0.f},{0.f,0.f}};

        #pragma unroll
        for (int idx = 0; idx < 12; idx++) {
            const int s = 12 * g + idx;
            const int mt = idx >> 1, h = idx & 1;
            const float cs = cuts[s];
            const int src = srcs[s], tgt = tgts[s];
            const float* xb = g_x + src * H3;
            float f0 = (d[mt][j][2 * h]     + b0)  * cs;
            float f1 = (d[mt][j][2 * h + 1] + b1v) * cs;

            if (part == 0) {
                float2 x2 = __ldg((const float2*)(xb + jj));
                a0 += x2.x * f0;
                a1 += x2.y * f1;
            } else if (part == 1) {
                float2 x2 = __ldg((const float2*)(xb + HID + jj));
                float t0 = x2.x * f0, t1 = x2.y * f1;
                #pragma unroll
                for (int dd = 0; dd < 3; dd++) {
                    float u = uvs[s * 3 + dd];
                    v[dd][0] += u * t0;
                    v[dd][1] += u * t1;
                }
            } else {
                float2 x2 = __ldg((const float2*)(xb + 2 * HID + jj));
                float t0 = x2.x * f0, t1 = x2.y * f1;
                #pragma unroll
                for (int dd = 0; dd < 3; dd++) {
                    float2 m2 = __ldg((const float2*)(mu + (src * 3 + dd) * HID + jj));
                    v[dd][0] += m2.x * t0;
                    v[dd][1] += m2.y * t1;
                }
            }

            const bool flush = (idx == 11) || (tgts[s + 1] != tgt);
            if (flush) {
                if (part == 0) {
                    red_add_v2(outq + tgt * HID + jj, a0, a1);
                    a0 = 0.f; a1 = 0.f;
                } else {
                    #pragma unroll
                    for (int dd = 0; dd < 3; dd++) {
                        red_add_v2(outmu + (tgt * 3 + dd) * HID + jj, v[dd][0], v[dd][1]);
                        v[dd][0] = 0.f; v[dd][1] = 0.f;
                    }
                }
            }
        }
    }
}

extern "C" void kernel_launch(void* const* d_in, const int* in_sizes, int n_in,
                              void* d_out, int out_size) {
    const float* q   = (const float*)d_in[0];
    const float* mu  = (const float*)d_in[1];
    const void*  ei  = d_in[2];
    const float* rbf = (const float*)d_in[3];
    const float* uvp = (const float*)d_in[4];
    const float* cut = (const float*)d_in[5];
    const float* W1  = (const float*)d_in[6];
    const float* b1  = (const float*)d_in[7];
    const float* W2  = (const float*)d_in[8];
    const float* b2  = (const float*)d_in[9];
    const float* Wf1 = (const float*)d_in[10];
    const float* bf1 = (const float*)d_in[11];
    const float* Wf2 = (const float*)d_in[12];
    const float* bf2 = (const float*)d_in[13];
    float* out = (float*)d_out;

    cudaFuncSetAttribute(edge_kernel,
                         cudaFuncAttributeMaxDynamicSharedMemorySize, SMEM_EDGE);
    cudaFuncSetAttribute(node_mma,
                         cudaFuncAttributeMaxDynamicSharedMemorySize, SMEM_NODE);

    const int total4 = N_NODES * (HID + H3) / 4;
    init_out<<<(total4 + 255) / 256, 256>>>(q, mu, out, (const int*)ei, Wf2, W1, W2);
    hist_kernel<<<(N_EDGES + 255) / 256, 256>>>((const int*)ei, (const long long*)ei);
    scan_kernel<<<1, 1024>>>();
    scatter_kernel<<<(N_EDGES + 255) / 256, 256>>>((const int*)ei, (const long long*)ei);
    node_mma<<<(N_NODES + NPB - 1) / NPB, 256, SMEM_NODE>>>(q, b1, b2);
    edge_kernel<<<(N_EDGES + EPB - 1) / EPB, EK_THREADS, SMEM_EDGE>>>(
        (const int*)ei, (const long long*)ei,
        rbf, uvp, cut, Wf1, bf1, bf2, mu, out);
}